// round 6
// baseline (speedup 1.0000x reference)
#include <cuda_runtime.h>

#define FULL 0xFFFFFFFFu
typedef unsigned long long u64;

// Per-block partials + completion counter (static device scratch).
__device__ float g_partials[512];
__device__ unsigned int g_cnt = 0;

// ---- f32x2 packed helpers (sm_100+ PTX) ----
__device__ __forceinline__ u64 pk(float lo, float hi) {
    u64 d; asm("mov.b64 %0, {%1, %2};" : "=l"(d) : "f"(lo), "f"(hi)); return d;
}
__device__ __forceinline__ float lo2(u64 d) { return __uint_as_float((unsigned)d); }
__device__ __forceinline__ float hi2(u64 d) { return __uint_as_float((unsigned)(d >> 32)); }
__device__ __forceinline__ u64 fma2(u64 a, u64 b, u64 c) {
    u64 d; asm("fma.rn.f32x2 %0, %1, %2, %3;" : "=l"(d) : "l"(a), "l"(b), "l"(c)); return d;
}
__device__ __forceinline__ u64 mul2(u64 a, u64 b) {
    u64 d; asm("mul.rn.f32x2 %0, %1, %2;" : "=l"(d) : "l"(a), "l"(b)); return d;
}

// Two batch elements per warp (16-lane segments), 4 states/lane in f32x2 pairs.
// Linear-space scaled forward. D-chain: constant prefix products folded into
// consumers; per-step 16-wide additive scan SPLIT into two parallel scans so
// the pUp shuffle is off the critical path:
//   u0[sl] (the shfl-dependent term) satisfies u0[sl+1] = y[sl],
//   y[sl] = (cc0[sl+1]*evx[sl+1]) * p3[sl]  -- lane-local given shifted LUTs.
//   Tfull = scanIncl(z) + scanIncl(y) - y,  z = u1+u2+u3.
__global__ void __launch_bounds__(128)
phmm_kernel(const int* __restrict__ xin,       // (B,128) int32 in [0,4)
            const float* __restrict__ trans,   // (B,65,7)
            const float* __restrict__ emis,    // (B,64,4)
            const float* __restrict__ mus,     // (B,16)
            const float* __restrict__ logvars, // (B,16)
            float* __restrict__ out)           // scalar
{
    const int lane = threadIdx.x & 31;
    const int sl   = lane & 15;            // lane within segment
    const int seg  = lane >> 4;            // which batch of this warp
    const int warp = threadIdx.x >> 5;
    const int b = blockIdx.x * 8 + warp * 2 + seg;

    __shared__ float4 sE4[4 * 4 * 32];     // [warp][sym][lane] emission quads
    __shared__ float  sEC[4 * 4 * 32];     // e[63] replicated
    __shared__ float  sEX[4 * 4 * 32];     // e[4sl+3] = next lane's ev.x (sl15->0)
    __shared__ int    sx[8 * 132];         // symbols, stride de-conflicts
    __shared__ float  sred[8];
    __shared__ int    sflag;
    __shared__ float  s2[128];

    int* sxw = &sx[(warp * 2 + seg) * 132];
    {
        const int* xb = xin + b * 128;
        #pragma unroll
        for (int i = 0; i < 8; i++) sxw[sl + 16 * i] = xb[sl + 16 * i];
    }

    // ---- transitions (order M2M,M2I,M2D,I2M,I2I,D2M,D2D), rows 4sl..4sl+3 ----
    const float* ab = trans + b * 455;
    const float* a0 = ab + 28 * sl;
    float tM2M[4], tqM2I[4], tI2M[4], tqI2I[4], tM2D[4], tD2M[4], tD2D[4];
    #pragma unroll
    for (int j = 0; j < 4; j++) {
        tM2M[j]  = __expf(a0[7 * j + 0]);
        tqM2I[j] = 0.25f * __expf(a0[7 * j + 1]);   // LOG_Q folded
        tM2D[j]  = __expf(a0[7 * j + 2]);
        tI2M[j]  = __expf(a0[7 * j + 3]);
        tqI2I[j] = 0.25f * __expf(a0[7 * j + 4]);
        tD2M[j]  = __expf(a0[7 * j + 5]);
        tD2D[j]  = __expf(a0[7 * j + 6]);
    }
    const float* a64 = ab + 64 * 7;
    float t64M2M  = __expf(a64[0]);
    float tq64M2I = 0.25f * __expf(a64[1]);
    float t64I2M  = __expf(a64[3]);
    float tq64I2I = 0.25f * __expf(a64[4]);
    float t64D2M  = __expf(a64[5]);

    // ---- emission LUTs ----
    const float* eb = emis + b * 256;
    {
        #pragma unroll
        for (int x = 0; x < 4; x++) {
            float4 v;
            v.x = (sl == 0) ? 0.0f : __expf(eb[(4 * sl - 1) * 4 + x]);
            v.y = __expf(eb[(4 * sl + 0) * 4 + x]);
            v.z = __expf(eb[(4 * sl + 1) * 4 + x]);
            v.w = __expf(eb[(4 * sl + 2) * 4 + x]);
            sE4[(warp * 4 + x) * 32 + lane] = v;
            sEC[(warp * 4 + x) * 32 + lane] = __expf(eb[63 * 4 + x]);
            // next lane's ev.x = e[4(sl+1)-1] = e[4sl+3]; sl=15 -> unused, 0
            sEX[(warp * 4 + x) * 32 + lane] =
                (sl == 15) ? 0.0f : __expf(eb[(4 * sl + 3) * 4 + x]);
        }
    }
    __syncwarp();

    // ---- prefix products of D-chain coefficients (constant in time) ----
    float P64fac, cc0v, cc1v, cc2v, cc3v, ccn;
    u64 dd01, dd23;
    {
        float q0 = tD2D[0], q01 = q0 * tD2D[1], q012 = q01 * tD2D[2], q0123 = q012 * tD2D[3];
        float Q = q0123;
        #pragma unroll
        for (int off = 1; off < 16; off <<= 1) {
            float q = __shfl_up_sync(FULL, Q, off, 16);
            if (sl >= off) Q *= q;
        }
        float Pex = __shfl_up_sync(FULL, Q, 1, 16);   // P[4sl]
        if (sl == 0) Pex = 1.0f;
        float Pa = Pex * q0, Pb = Pex * q01, Pc = Pex * q012, Pd = Pex * q0123;
        dd01 = pk(tD2M[0] * Pex, tD2M[1] * Pa);
        dd23 = pk(tD2M[2] * Pb,  tD2M[3] * Pc);
        cc0v = __fdividef(tM2D[0], Pa);
        cc1v = __fdividef(tM2D[1], Pb);
        cc2v = __fdividef(tM2D[2], Pc);
        cc3v = __fdividef(tM2D[3], Pd);
        ccn = __shfl_down_sync(FULL, cc0v, 1, 16);    // cc0 of next lane
        if (sl == 15) ccn = 0.0f;
        P64fac = Pd;                        // on sl=15: P[64]
    }
    const u64 tM2M01  = pk(tM2M[0], tM2M[1]),   tM2M23  = pk(tM2M[2], tM2M[3]);
    const u64 tI2M01  = pk(tI2M[0], tI2M[1]),   tI2M23  = pk(tI2M[2], tI2M[3]);
    const u64 tqI2I01 = pk(tqI2I[0], tqI2I[1]), tqI2I23 = pk(tqI2I[2], tqI2I[3]);
    const u64 tqM2I01 = pk(tqM2I[0], tqM2I[1]), tqM2I23 = pk(tqM2I[2], tqM2I[3]);

    // ---- init states ----
    u64 FM01 = pk((sl == 0) ? 1.0f : 0.0f, 0.0f), FM23 = pk(0.0f, 0.0f);
    u64 FI01 = pk(0.0f, 0.0f), FI23 = pk(0.0f, 0.0f);
    float FM64 = 0.0f, FI64 = 0.0f;
    u64 w01, w23, PRE01, PRE23;
    float incl, S = 0.0f;

    unsigned sE4a = (unsigned)__cvta_generic_to_shared(&sE4[warp * 128 + lane]);
    const float* sECw = &sEC[warp * 128 + lane];
    const float* sEXw = &sEX[warp * 128 + lane];

    // initial D-chain (latency irrelevant here): plain single scan
    {
        float u0 = cc0v * lo2(FM01), u1 = cc1v * hi2(FM01);
        float u2 = cc2v * lo2(FM23), u3 = cc3v * hi2(FM23);
        float s0 = u0, s1 = s0 + u1, s2 = s1 + u2, s3 = s2 + u3;
        float T = s3;
        #pragma unroll
        for (int off = 1; off < 16; off <<= 1) {
            float t = __shfl_up_sync(FULL, T, off, 16);
            if (sl >= off) T += t;
        }
        incl = T;
        float ex = T - s3;
        w01 = pk(ex, ex + s0);
        w23 = pk(ex + s1, ex + s2);
        PRE01 = fma2(tI2M01, FI01, mul2(tM2M01, FM01));
        PRE23 = fma2(tI2M23, FI23, mul2(tM2M23, FM23));
    }

#define STEP(x)                                                               \
    {                                                                         \
        u64 ev01, ev23;                                                       \
        asm("ld.shared.v2.u64 {%0, %1}, [%2];"                                \
            : "=l"(ev01), "=l"(ev23) : "r"(sE4a + (unsigned)(x) * 512));      \
        float eC  = sECw[(x) * 32];                                           \
        float evx = sEXw[(x) * 32];                                           \
        float ykc = ccn * evx;              /* off-path */                    \
        float zc1 = cc1v * hi2(ev01);                                         \
        float zc2 = cc2v * lo2(ev23);                                         \
        float zc3 = cc3v * hi2(ev23);                                         \
        u64 p01 = fma2(dd01, w01, PRE01);                                     \
        u64 p23 = fma2(dd23, w23, PRE23);                                     \
        float p0 = lo2(p01), p1 = hi2(p01), p2 = lo2(p23), p3 = hi2(p23);     \
        float y  = ykc * p3;                                                  \
        float u1 = zc1 * p0, u2 = zc2 * p1, u3 = zc3 * p2;                    \
        float z  = (u1 + u2) + u3;                                            \
        float Tz = z, Ty = y;                                                 \
        _Pragma("unroll")                                                     \
        for (int off = 1; off < 16; off <<= 1) {                              \
            float tz = __shfl_up_sync(FULL, Tz, off, 16);                     \
            float ty = __shfl_up_sync(FULL, Ty, off, 16);                     \
            if (sl >= off) { Tz += tz; Ty += ty; }                            \
        }                                                                     \
        float pUp = __shfl_up_sync(FULL, p3, 1, 16);   /* parallel to scan */ \
        float FM0 = lo2(ev01) * pUp;        /* sl0: ev.x==0 -> 0 */           \
        float u0  = cc0v * FM0;                                               \
        FI01 = fma2(tqI2I01, FI01, mul2(tqM2I01, FM01));  /* OLD FM */        \
        FI23 = fma2(tqI2I23, FI23, mul2(tqM2I23, FM23));                      \
        FI64 = fmaf(tq64I2I, FI64, tq64M2I * FM64);                           \
        FM01 = mul2(ev01, pk(pUp, p0));                                       \
        FM23 = mul2(ev23, pk(p1, p2));                                        \
        FM64 = eC * p3;                     /* valid on sl=15 */              \
        float Tfull = Tz + (Ty - y);                                          \
        incl = Tfull;                                                         \
        float s3 = (u0 + u1) + (u2 + u3);                                     \
        float w0 = Tfull - s3;                                                \
        float w1 = w0 + u0, w2 = w1 + u1, w3 = w2 + u2;                       \
        w01 = pk(w0, w1); w23 = pk(w2, w3);                                   \
        PRE01 = fma2(tI2M01, FI01, mul2(tM2M01, FM01));  /* off-path */       \
        PRE23 = fma2(tI2M23, FI23, mul2(tM2M23, FM23));                       \
    }

    #pragma unroll 1
    for (int lq = 0; lq < 16; lq++) {
        int4 xa = *(const int4*)&sxw[8 * lq];
        int4 xb4 = *(const int4*)&sxw[8 * lq + 4];
        STEP(xa.x); STEP(xa.y); STEP(xa.z); STEP(xa.w);
        STEP(xb4.x); STEP(xb4.y); STEP(xb4.z); STEP(xb4.w);
        // rescale by segment max
        float m = fmaxf(fmaxf(lo2(FM01), hi2(FM01)), fmaxf(lo2(FM23), hi2(FM23)));
        m = fmaxf(m, fmaxf(fmaxf(lo2(FI01), hi2(FI01)), fmaxf(lo2(FI23), hi2(FI23))));
        m = fmaxf(m, fmaxf(FM64, FI64));
        #pragma unroll
        for (int off = 1; off < 16; off <<= 1)
            m = fmaxf(m, __shfl_xor_sync(FULL, m, off, 16));
        m = fmaxf(m, 1e-30f);
        float r = 1.0f / m;
        S += __logf(m);
        u64 rr = pk(r, r);
        FM01 = mul2(FM01, rr); FM23 = mul2(FM23, rr);
        FI01 = mul2(FI01, rr); FI23 = mul2(FI23, rr);
        w01 = mul2(w01, rr);   w23 = mul2(w23, rr);
        PRE01 = mul2(PRE01, rr); PRE23 = mul2(PRE23, rr);  // linear in states
        FM64 *= r; FI64 *= r; incl *= r;
    }

    // ---- final: three end transitions (sl=15 holds state 64 & full prefix) ----
    float fdTop = P64fac * incl;
    float Pfin = fmaf(t64D2M, fdTop, fmaf(t64I2M, FI64, t64M2M * FM64));
    float loss = -(S + __logf(Pfin));             // valid on sl=15

    // ---- KLD: 16 segment lanes, one latent dim each ----
    float kt;
    {
        float mu = mus[b * 16 + sl];
        float lv = logvars[b * 16 + sl];
        kt = 1.0f + lv - mu * mu - __expf(lv);
    }
    #pragma unroll
    for (int off = 1; off < 16; off <<= 1)
        kt += __shfl_xor_sync(FULL, kt, off, 16);

    if (sl == 15) sred[warp * 2 + seg] = loss - 0.5f * kt;
    __syncthreads();
    if (threadIdx.x == 0) {
        float v = ((sred[0] + sred[1]) + (sred[2] + sred[3]))
                + ((sred[4] + sred[5]) + (sred[6] + sred[7]));
        g_partials[blockIdx.x] = v;
        __threadfence();
        unsigned t = atomicAdd(&g_cnt, 1u);
        sflag = (t == gridDim.x - 1) ? 1 : 0;
    }
    __syncthreads();
    if (sflag) {
        float s = 0.0f;
        #pragma unroll
        for (int i = 0; i < 4; i++)
            s += __ldcg(&g_partials[threadIdx.x + 128 * i]);
        s2[threadIdx.x] = s;
        __syncthreads();
        #pragma unroll
        for (int st = 64; st; st >>= 1) {
            if (threadIdx.x < st) s2[threadIdx.x] += s2[threadIdx.x + st];
            __syncthreads();
        }
        if (threadIdx.x == 0) {
            out[0] = s2[0] * (1.0f / 4096.0f);
            g_cnt = 0;  // self-reset for graph replay
        }
    }
#undef STEP
}

extern "C" void kernel_launch(void* const* d_in, const int* in_sizes, int n_in,
                              void* d_out, int out_size) {
    const int*   x  = (const int*)d_in[0];    // batch_input (B,128)
    const float* a  = (const float*)d_in[1];  // transition_probs (B,65,7)
    const float* e  = (const float*)d_in[2];  // emission_probs (B,64,4)
    const float* mu = (const float*)d_in[3];  // mus (B,16)
    const float* lv = (const float*)d_in[4];  // logvars (B,16)
    const int B = in_sizes[0] / 128;          // 4096
    phmm_kernel<<<B / 8, 128>>>(x, a, e, mu, lv, (float*)d_out);
}

// round 7
// speedup vs baseline: 1.1739x; 1.1739x over previous
#include <cuda_runtime.h>

#define FULL 0xFFFFFFFFu
typedef unsigned long long u64;

// Per-block partials + completion counter (static device scratch).
__device__ float g_partials[1024];
__device__ unsigned int g_cnt = 0;

// ---- f32x2 packed helpers (sm_100+ PTX) ----
__device__ __forceinline__ u64 pk(float lo, float hi) {
    u64 d; asm("mov.b64 %0, {%1, %2};" : "=l"(d) : "f"(lo), "f"(hi)); return d;
}
__device__ __forceinline__ float lo2(u64 d) { return __uint_as_float((unsigned)d); }
__device__ __forceinline__ float hi2(u64 d) { return __uint_as_float((unsigned)(d >> 32)); }
__device__ __forceinline__ u64 fma2(u64 a, u64 b, u64 c) {
    u64 d; asm("fma.rn.f32x2 %0, %1, %2, %3;" : "=l"(d) : "l"(a), "l"(b), "l"(c)); return d;
}
__device__ __forceinline__ u64 mul2(u64 a, u64 b) {
    u64 d; asm("mul.rn.f32x2 %0, %1, %2;" : "=l"(d) : "l"(a), "l"(b)); return d;
}

// One batch per warp. Lane L owns states k0=2L, k1=2L+1 packed in one f32x2
// pair; state 64 carried scalar (lane 31 valid). Linear-space scaled forward;
// D-chain via constant prefix products folded into consumers; single 32-wide
// additive scan (5 shfl stages) per step.
__global__ void __launch_bounds__(128)
phmm_kernel(const int* __restrict__ xin,       // (B,128) int32 in [0,4)
            const float* __restrict__ trans,   // (B,65,7)
            const float* __restrict__ emis,    // (B,64,4)
            const float* __restrict__ mus,     // (B,16)
            const float* __restrict__ logvars, // (B,16)
            float* __restrict__ out)           // scalar
{
    const int lane = threadIdx.x & 31;
    const int warp = threadIdx.x >> 5;
    const int b = blockIdx.x * 4 + warp;

    __shared__ u64   sEV[4 * 4 * 32];      // [warp][sym][lane]: (e[2L-1], e[2L])
    __shared__ float sEC[4 * 4 * 32];      // e[63] replicated
    __shared__ int   sx[4 * 132];          // symbols, stride de-conflicts
    __shared__ float sred[4];
    __shared__ int   sflag;
    __shared__ float s2[128];

    int* sxw = &sx[warp * 132];
    {
        const int* xb = xin + b * 128;
        #pragma unroll
        for (int i = 0; i < 4; i++) sxw[lane + 32 * i] = xb[lane + 32 * i];
    }

    // ---- transitions (order M2M,M2I,M2D,I2M,I2I,D2M,D2D), rows 2L, 2L+1 ----
    const float* ab = trans + b * 455;
    const float* a0 = ab + 14 * lane;
    float tM2M0  = __expf(a0[0]),  tM2M1  = __expf(a0[7]);
    float tqM2I0 = 0.25f * __expf(a0[1]),  tqM2I1 = 0.25f * __expf(a0[8]);
    float tM2D0  = __expf(a0[2]),  tM2D1  = __expf(a0[9]);
    float tI2M0  = __expf(a0[3]),  tI2M1  = __expf(a0[10]);
    float tqI2I0 = 0.25f * __expf(a0[4]),  tqI2I1 = 0.25f * __expf(a0[11]);
    float tD2M0  = __expf(a0[5]),  tD2M1  = __expf(a0[12]);
    float tD2D0  = __expf(a0[6]),  tD2D1  = __expf(a0[13]);
    const float* a64 = ab + 64 * 7;
    float t64M2M  = __expf(a64[0]);
    float tq64M2I = 0.25f * __expf(a64[1]);
    float t64I2M  = __expf(a64[3]);
    float tq64I2I = 0.25f * __expf(a64[4]);
    float t64D2M  = __expf(a64[5]);

    // ---- emission LUTs ----
    // FM_new[2L] needs e[2L-1] (lane0 entry = 0 so state0 stays 0),
    // FM_new[2L+1] needs e[2L], FM_new[64] needs e[63].
    const float* eb = emis + b * 256;
    {
        #pragma unroll
        for (int x = 0; x < 4; x++) {
            float vA = (lane == 0) ? 0.0f : __expf(eb[(2 * lane - 1) * 4 + x]);
            float vB = __expf(eb[(2 * lane) * 4 + x]);
            sEV[(warp * 4 + x) * 32 + lane] = pk(vA, vB);
            sEC[(warp * 4 + x) * 32 + lane] = __expf(eb[63 * 4 + x]);
        }
    }
    __syncwarp();   // each warp touches only its own rows

    // ---- prefix products of D-chain coefficients (constant in time) ----
    // fD[k] = tM2D[k-1]*fM[k-1] + tD2D[k-1]*fD[k-1]; P[k] = prod tD2D[<k].
    float P64fac;
    u64 cc01, dd01;
    {
        float q0 = tD2D0, q01 = q0 * tD2D1;
        float Q = q01;
        #pragma unroll
        for (int off = 1; off < 32; off <<= 1) {
            float q = __shfl_up_sync(FULL, Q, off);
            if (lane >= off) Q *= q;
        }
        float Pex = __shfl_up_sync(FULL, Q, 1);   // P[2L]
        if (lane == 0) Pex = 1.0f;
        float Pa = Pex * q0;                      // P[2L+1]
        float Pb = Pex * q01;                     // P[2L+2]
        dd01 = pk(tD2M0 * Pex, tD2M1 * Pa);
        cc01 = pk(__fdividef(tM2D0, Pa), __fdividef(tM2D1, Pb));
        P64fac = Pb;                              // lane 31: P[64]
    }
    const u64 tM2M01  = pk(tM2M0, tM2M1);
    const u64 tI2M01  = pk(tI2M0, tI2M1);
    const u64 tqI2I01 = pk(tqI2I0, tqI2I1);
    const u64 tqM2I01 = pk(tqM2I0, tqM2I1);

    // ---- init states ----
    u64 FM01 = pk((lane == 0) ? 1.0f : 0.0f, 0.0f);
    u64 FI01 = pk(0.0f, 0.0f);
    float FM64 = 0.0f, FI64 = 0.0f;
    u64 w01, PRE01;
    float incl, S = 0.0f;

    unsigned sEVa = (unsigned)__cvta_generic_to_shared(&sEV[warp * 128 + lane]);
    const float* sECw = &sEC[warp * 128 + lane];

    // initial D-chain + PRE
    {
        u64 u01 = mul2(cc01, FM01);
        float u0 = lo2(u01), u1 = hi2(u01);
        float s1 = u0 + u1;
        float T = s1;
        #pragma unroll
        for (int off = 1; off < 32; off <<= 1) {
            float t = __shfl_up_sync(FULL, T, off);
            if (lane >= off) T += t;
        }
        incl = T;
        float ex = T - s1;
        w01 = pk(ex, ex + u0);
        PRE01 = fma2(tI2M01, FI01, mul2(tM2M01, FM01));
    }

#define STEP(x)                                                               \
    {                                                                         \
        u64 ev01;                                                             \
        asm("ld.shared.u64 %0, [%1];"                                         \
            : "=l"(ev01) : "r"(sEVa + (unsigned)(x) * 256));                  \
        float eC = sECw[(x) * 32];                                            \
        u64 p01 = fma2(dd01, w01, PRE01);                                     \
        float p0 = lo2(p01), p1 = hi2(p01);                                   \
        float pUp = __shfl_up_sync(FULL, p1, 1);                              \
        FI01 = fma2(tqI2I01, FI01, mul2(tqM2I01, FM01));  /* OLD FM */        \
        FI64 = fmaf(tq64I2I, FI64, tq64M2I * FM64);                           \
        FM01 = mul2(ev01, pk(pUp, p0));     /* lane0: ev.x==0 -> 0 */         \
        FM64 = eC * p1;                     /* valid on lane 31 */            \
        u64 u01 = mul2(cc01, FM01);                                           \
        float u0 = lo2(u01), u1 = hi2(u01);                                   \
        float s1 = u0 + u1;                                                   \
        float T = s1;                                                         \
        _Pragma("unroll")                                                     \
        for (int off = 1; off < 32; off <<= 1) {                              \
            float t = __shfl_up_sync(FULL, T, off);                           \
            if (lane >= off) T += t;                                          \
        }                                                                     \
        incl = T;                                                             \
        float ex = T - s1;                                                    \
        w01 = pk(ex, ex + u0);                                                \
        PRE01 = fma2(tI2M01, FI01, mul2(tM2M01, FM01));                       \
    }

    #pragma unroll 1
    for (int lq = 0; lq < 16; lq++) {
        int4 xa = *(const int4*)&sxw[8 * lq];
        int4 xb4 = *(const int4*)&sxw[8 * lq + 4];
        STEP(xa.x); STEP(xa.y); STEP(xa.z); STEP(xa.w);
        STEP(xb4.x); STEP(xb4.y); STEP(xb4.z); STEP(xb4.w);
        // rescale by warp max
        float m = fmaxf(fmaxf(lo2(FM01), hi2(FM01)), fmaxf(lo2(FI01), hi2(FI01)));
        m = fmaxf(m, fmaxf(FM64, FI64));
        #pragma unroll
        for (int off = 16; off; off >>= 1)
            m = fmaxf(m, __shfl_xor_sync(FULL, m, off));
        m = fmaxf(m, 1e-30f);
        float r = 1.0f / m;
        S += __logf(m);
        u64 rr = pk(r, r);
        FM01 = mul2(FM01, rr); FI01 = mul2(FI01, rr);
        w01 = mul2(w01, rr);   PRE01 = mul2(PRE01, rr);  // linear in states
        FM64 *= r; FI64 *= r; incl *= r;
    }

    // ---- final: three end transitions (lane 31 holds state 64 & full prefix) ----
    float fdTop = P64fac * incl;
    float Pfin = fmaf(t64D2M, fdTop, fmaf(t64I2M, FI64, t64M2M * FM64));
    float loss = -(S + __logf(Pfin));             // valid on lane 31

    // ---- KLD: lanes 0..15 each handle one latent dim ----
    float kt = 0.0f;
    if (lane < 16) {
        float mu = mus[b * 16 + lane];
        float lv = logvars[b * 16 + lane];
        kt = 1.0f + lv - mu * mu - __expf(lv);
    }
    #pragma unroll
    for (int off = 16; off; off >>= 1)
        kt += __shfl_xor_sync(FULL, kt, off);

    if (lane == 31) sred[warp] = loss - 0.5f * kt;
    __syncthreads();
    if (threadIdx.x == 0) {
        float v = (sred[0] + sred[1]) + (sred[2] + sred[3]);
        g_partials[blockIdx.x] = v;
        __threadfence();
        unsigned t = atomicAdd(&g_cnt, 1u);
        sflag = (t == gridDim.x - 1) ? 1 : 0;
    }
    __syncthreads();
    if (sflag) {
        float s = 0.0f;
        #pragma unroll
        for (int i = 0; i < 8; i++)
            s += __ldcg(&g_partials[threadIdx.x + 128 * i]);
        s2[threadIdx.x] = s;
        __syncthreads();
        #pragma unroll
        for (int st = 64; st; st >>= 1) {
            if (threadIdx.x < st) s2[threadIdx.x] += s2[threadIdx.x + st];
            __syncthreads();
        }
        if (threadIdx.x == 0) {
            out[0] = s2[0] * (1.0f / 4096.0f);
            g_cnt = 0;  // self-reset for graph replay
        }
    }
#undef STEP
}

extern "C" void kernel_launch(void* const* d_in, const int* in_sizes, int n_in,
                              void* d_out, int out_size) {
    const int*   x  = (const int*)d_in[0];    // batch_input (B,128)
    const float* a  = (const float*)d_in[1];  // transition_probs (B,65,7)
    const float* e  = (const float*)d_in[2];  // emission_probs (B,64,4)
    const float* mu = (const float*)d_in[3];  // mus (B,16)
    const float* lv = (const float*)d_in[4];  // logvars (B,16)
    const int B = in_sizes[0] / 128;          // 4096
    phmm_kernel<<<B / 4, 128>>>(x, a, e, mu, lv, (float*)d_out);
}